// round 9
// baseline (speedup 1.0000x reference)
#include <cuda_runtime.h>
#include <cuda_bf16.h>
#include <math.h>

// Problem constants
#define B_  16
#define CIN 512
#define L_  1024
#define COUT 1024
#define K_  5
#define DW  512
#define HW  196
#define KCONV (CIN * K_)   // 2560
#define PP  224            // padded p dimension (HW=196 -> 224)

// Output layout (concatenated tuple): out, word_embed, img_conv, attn
#define OUT_WE   8388608u          // 16*512*1024
#define OUT_IMG  16777216u         // + 16*1024*512
#define OUT_ATTN 18382848u         // + 16*512*196

typedef __nv_bfloat16 bf16;

// ---------------------------------------------------------------------------
// Scratch (device globals; allocation-free rule)
// ---------------------------------------------------------------------------
__device__ float g_w[COUT * KCONV];          // normalized conv weights (co, c, t)
__device__ float g_h[B_ * DW * L_];          // GLU output fp32 (b, ch, l)
__device__ bf16 g_xh[B_ * CIN * L_],  g_xl[B_ * CIN * L_];    // x split
__device__ bf16 g_cwh[COUT * KCONV], g_cwl[COUT * KCONV];     // conv W reordered+split
__device__ bf16 g_w1h[DW * DW], g_w1l[DW * DW];               // fc1 W split [a][c]
__device__ bf16 g_w2h[DW * DW], g_w2l[DW * DW];               // fc2 W split [c][a]
__device__ bf16 g_hh[B_ * DW * L_], g_hl[B_ * DW * L_];       // h split (b, ch, l)
__device__ bf16 g_qh[B_ * L_ * DW], g_ql[B_ * L_ * DW];       // q split (b, l, a)
__device__ bf16 g_cxh[B_ * DW * L_], g_cxl[B_ * DW * L_];     // ctx split (b, a, l)
__device__ bf16 g_fTh[B_ * PP * DW], g_fTl[B_ * PP * DW];     // feat^T split (b, p, a)
__device__ bf16 g_fh[B_ * DW * PP],  g_fl[B_ * DW * PP];      // feat split (b, a, p)

__device__ __forceinline__ void split2(float v, bf16& h, bf16& l) {
    h = __float2bfloat16(v);
    l = __float2bfloat16(v - __bfloat162float(h));
}

__device__ __forceinline__ void cp16(void* dst, const void* src) {
    unsigned d = (unsigned)__cvta_generic_to_shared(dst);
    asm volatile("cp.async.cg.shared.global [%0], [%1], 16;\n" :: "r"(d), "l"(src));
}
#define CP_COMMIT() asm volatile("cp.async.commit_group;\n")
#define CP_WAIT0()  asm volatile("cp.async.wait_group 0;\n")

// ---------------------------------------------------------------------------
// Kernel 1: weight norm.
// ---------------------------------------------------------------------------
__global__ void wnorm_kernel(const float* __restrict__ v,
                             const float* __restrict__ g) {
    int co = blockIdx.x;
    const float* vr = v + (size_t)co * KCONV;
    float s = 0.f;
    for (int i = threadIdx.x; i < KCONV; i += 256) {
        float t = vr[i];
        s += t * t;
    }
    __shared__ float red[256];
    red[threadIdx.x] = s;
    __syncthreads();
    for (int st = 128; st > 0; st >>= 1) {
        if (threadIdx.x < st) red[threadIdx.x] += red[threadIdx.x + st];
        __syncthreads();
    }
    float scale = g[co] / sqrtf(red[0]);
    float* wr = g_w + (size_t)co * KCONV;
    for (int i = threadIdx.x; i < KCONV; i += 256) wr[i] = scale * vr[i];
}

// ---------------------------------------------------------------------------
// Kernel 1b: reorder conv weights to A[m][kk], kk = t*512 + c, split to bf16.
// ---------------------------------------------------------------------------
__global__ void convw_split_kernel() {
    int m = blockIdx.x;
    int co = (m & 1) ? (512 + (m >> 1)) : (m >> 1);
    const float* wr = g_w + (size_t)co * KCONV;
    for (int kk = threadIdx.x; kk < KCONV; kk += 256) {
        int t = kk >> 9, c = kk & 511;
        float v = wr[c * K_ + t];
        bf16 hi, lo; split2(v, hi, lo);
        g_cwh[(size_t)m * KCONV + kk] = hi;
        g_cwl[(size_t)m * KCONV + kk] = lo;
    }
}

// ---------------------------------------------------------------------------
// Kernel 1c: generic fp32 -> bf16 hi/lo split
// ---------------------------------------------------------------------------
__global__ void split_kernel(const float* __restrict__ src,
                             bf16* __restrict__ dh, bf16* __restrict__ dl, int n) {
    int i = blockIdx.x * blockDim.x + threadIdx.x;
    int stride = gridDim.x * blockDim.x;
    for (; i < n; i += stride) {
        bf16 hi, lo; split2(src[i], hi, lo);
        dh[i] = hi; dl[i] = lo;
    }
}

// ---------------------------------------------------------------------------
// Kernel 1d: feat^T split (b, p, a); p>=196 rows zero.
// ---------------------------------------------------------------------------
__global__ void featT_kernel(const float* __restrict__ img) {
    __shared__ float t[32][33];
    const int b = blockIdx.z, p0 = blockIdx.x * 32, a0 = blockIdx.y * 32;
    const int tx = threadIdx.x, ty0 = threadIdx.y;
#pragma unroll
    for (int j = 0; j < 4; j++) {
        int ty = ty0 + j * 8;
        int a = a0 + ty, p = p0 + tx;
        t[ty][tx] = (p < HW) ? img[((size_t)b * 512 + a) * HW + p] : 0.f;
    }
    __syncthreads();
#pragma unroll
    for (int j = 0; j < 4; j++) {
        int ty = ty0 + j * 8;
        float v = t[tx][ty];
        bf16 hi, lo; split2(v, hi, lo);
        size_t off = ((size_t)b * PP + p0 + ty) * 512 + a0 + tx;
        g_fTh[off] = hi; g_fTl[off] = lo;
    }
}

// ---------------------------------------------------------------------------
// Kernel 1e: feat split + p-pad (b, a, PP)
// ---------------------------------------------------------------------------
__global__ void featpad_kernel(const float* __restrict__ img) {
    int idx = blockIdx.x * 256 + threadIdx.x;
    if (idx >= B_ * 512 * PP) return;
    int p = idx % PP, ba = idx / PP;
    float v = (p < HW) ? img[(size_t)ba * HW + p] : 0.f;
    bf16 hi, lo; split2(v, hi, lo);
    g_fh[idx] = hi; g_fl[idx] = lo;
}

// ---------------------------------------------------------------------------
// Unified bf16-split tensor-core GEMM, software-pipelined (R9).
//   A smem [m=128][k=32] pitch 40 bf16, staged by cp.async, double-buffered.
//   B smem interleaved k-pairs: [k2=16][n=128] b32 pairs {B[2k2][n],B[2k2+1][n]},
//     pitch 136 words (conflict-free fragment loads), staged via register
//     prefetch (LDG overlapped with MMAs, STS after).
// ---------------------------------------------------------------------------
#define BM 128
#define BN 128
#define BK 32
#define APAD 40          // A smem pitch (bf16 elems); also used by attn kernel
#define BPITCH 136       // B smem pitch (b32 pairs)
#define A_PLANE 10240    // 128*40*2 bytes
#define B_PLANE 8704     // 16*136*4 bytes
#define STAGE_BYTES 37888
#define GEMM_SMEM (2 * STAGE_BYTES)   // 75776

__device__ __forceinline__ void mma_bf16(float* c, const unsigned* a,
                                         unsigned b0, unsigned b1) {
    asm volatile(
        "mma.sync.aligned.m16n8k16.row.col.f32.bf16.bf16.f32 "
        "{%0,%1,%2,%3}, {%4,%5,%6,%7}, {%8,%9}, {%0,%1,%2,%3};\n"
        : "+f"(c[0]), "+f"(c[1]), "+f"(c[2]), "+f"(c[3])
        : "r"(a[0]), "r"(a[1]), "r"(a[2]), "r"(a[3]), "r"(b0), "r"(b1));
}

template <int MODE>
__global__ __launch_bounds__(256, 2) void gemm_kernel(
    const float* __restrict__ bias,   // conv_b / fc1_b / fc2_b
    const float* __restrict__ e1,     // unused / we / x
    float* __restrict__ outp) {       // unused / unused / out
    const int KD = (MODE == 0) ? KCONV : 512;
    const bf16* Agh = (MODE == 0) ? g_cwh : (MODE == 1) ? g_w1h : g_w2h;
    const bf16* Agl = (MODE == 0) ? g_cwl : (MODE == 1) ? g_w1l : g_w2l;
    const bf16* Bh_base = (MODE == 0) ? g_xh : (MODE == 1) ? g_hh : g_cxh;
    const bf16* Bl_base = (MODE == 0) ? g_xl : (MODE == 1) ? g_hl : g_cxl;

    const int b  = blockIdx.z;
    const int m0 = blockIdx.y * BM;
    const int l0 = blockIdx.x * BN;
    const int tid = threadIdx.x;
    const int lane = tid & 31, warp = tid >> 5;
    const int wm = warp >> 1, wn = warp & 1;

    extern __shared__ __align__(16) unsigned char dynsm[];
    float* Cs = (float*)dynsm;   // epilogue alias [128][65]

    const bf16* Bgh = Bh_base + (size_t)b * 512 * L_;
    const bf16* Bgl = Bl_base + (size_t)b * 512 * L_;
    const unsigned short* Bgh_u = (const unsigned short*)Bgh;
    const unsigned short* Bgl_u = (const unsigned short*)Bgl;

    float acc[2][8][4];
#pragma unroll
    for (int mt = 0; mt < 2; mt++)
#pragma unroll
        for (int nt = 0; nt < 8; nt++)
#pragma unroll
            for (int j = 0; j < 4; j++) acc[mt][nt][j] = 0.f;

    unsigned rb[16];

    // ---- staging lambdas (by macro-ish inline) ----
    auto stageA = [&](int s, int k0) {
        bf16* Ah = (bf16*)(dynsm + s * STAGE_BYTES);
        bf16* Al = (bf16*)(dynsm + s * STAGE_BYTES + A_PLANE);
#pragma unroll
        for (int i = 0; i < 4; i++) {
            int c = i * 256 + tid;            // 1024 chunks: plane(1) x row(128) x j(4)
            int plane = c >> 9, rem = c & 511;
            int row = rem >> 2, j = rem & 3;
            const bf16* src = (plane ? Agl : Agh) + (size_t)(m0 + row) * KD + k0 + j * 8;
            bf16* dst = (plane ? Al : Ah) + row * APAD + j * 8;
            cp16(dst, src);
        }
    };

    auto loadB = [&](int k0) {
        if (MODE == 0) {
            int t = k0 >> 9, c0 = k0 & 511, sh = t - 4;
#pragma unroll
            for (int i = 0; i < 8; i++) {
                int u = i * 256 + tid;        // 2048 units (k2, n)
                int k2 = u >> 7, n = u & 127;
                int c = c0 + k2 * 2;
                int l = l0 + n + sh;
                unsigned h0 = 0, h1 = 0, q0 = 0, q1 = 0;
                if (l >= 0) {
                    size_t o0 = (size_t)c * L_ + l;
                    size_t o1 = o0 + L_;
                    h0 = Bgh_u[o0]; h1 = Bgh_u[o1];
                    q0 = Bgl_u[o0]; q1 = Bgl_u[o1];
                }
                rb[2 * i]     = h0 | (h1 << 16);
                rb[2 * i + 1] = q0 | (q1 << 16);
            }
        } else {
#pragma unroll
            for (int i = 0; i < 4; i++) {
                int u = i * 256 + tid;        // 1024 units (k2, npair)
                int k2 = u >> 6, np = u & 63;
                int n = np * 2;
                size_t o0 = (size_t)(k0 + k2 * 2) * L_ + l0 + n;
                size_t o1 = o0 + L_;
                unsigned h0 = *(const unsigned*)&Bgh[o0];
                unsigned h1 = *(const unsigned*)&Bgh[o1];
                unsigned q0 = *(const unsigned*)&Bgl[o0];
                unsigned q1 = *(const unsigned*)&Bgl[o1];
                rb[4 * i]     = __byte_perm(h0, h1, 0x5410);
                rb[4 * i + 1] = __byte_perm(h0, h1, 0x7632);
                rb[4 * i + 2] = __byte_perm(q0, q1, 0x5410);
                rb[4 * i + 3] = __byte_perm(q0, q1, 0x7632);
            }
        }
    };

    auto storeB = [&](int s) {
        unsigned* Bh = (unsigned*)(dynsm + s * STAGE_BYTES + 2 * A_PLANE);
        unsigned* Bl = (unsigned*)(dynsm + s * STAGE_BYTES + 2 * A_PLANE + B_PLANE);
        if (MODE == 0) {
#pragma unroll
            for (int i = 0; i < 8; i++) {
                int u = i * 256 + tid;
                int k2 = u >> 7, n = u & 127;
                Bh[k2 * BPITCH + n] = rb[2 * i];
                Bl[k2 * BPITCH + n] = rb[2 * i + 1];
            }
        } else {
#pragma unroll
            for (int i = 0; i < 4; i++) {
                int u = i * 256 + tid;
                int k2 = u >> 6, np = u & 63;
                int n = np * 2;
                *(uint2*)&Bh[k2 * BPITCH + n] = make_uint2(rb[4 * i], rb[4 * i + 1]);
                *(uint2*)&Bl[k2 * BPITCH + n] = make_uint2(rb[4 * i + 2], rb[4 * i + 3]);
            }
        }
    };

    // ---- prologue: stage 0 ----
    stageA(0, 0);
    CP_COMMIT();
    loadB(0);
    storeB(0);

    int cur = 0;
    for (int k0 = 0; k0 < KD; k0 += BK) {
        const bool more = (k0 + BK < KD);
        CP_WAIT0();
        __syncthreads();

        if (more) {
            stageA(cur ^ 1, k0 + BK);
            CP_COMMIT();
            loadB(k0 + BK);
        }

        // ---- compute from stage cur ----
        const bf16* Ahc = (const bf16*)(dynsm + cur * STAGE_BYTES);
        const bf16* Alc = (const bf16*)(dynsm + cur * STAGE_BYTES + A_PLANE);
        const unsigned* Bhc = (const unsigned*)(dynsm + cur * STAGE_BYTES + 2 * A_PLANE);
        const unsigned* Blc = (const unsigned*)(dynsm + cur * STAGE_BYTES + 2 * A_PLANE + B_PLANE);

#pragma unroll
        for (int ks = 0; ks < 2; ks++) {
            const int kb = ks * 16 + (lane & 3) * 2;
            const int krow = ks * 8 + (lane & 3);
            unsigned ah[2][4], al[2][4];
#pragma unroll
            for (int mt = 0; mt < 2; mt++) {
                int rbw = wm * 32 + mt * 16 + (lane >> 2);
                ah[mt][0] = *(const unsigned*)&Ahc[rbw * APAD + kb];
                ah[mt][1] = *(const unsigned*)&Ahc[(rbw + 8) * APAD + kb];
                ah[mt][2] = *(const unsigned*)&Ahc[rbw * APAD + kb + 8];
                ah[mt][3] = *(const unsigned*)&Ahc[(rbw + 8) * APAD + kb + 8];
                al[mt][0] = *(const unsigned*)&Alc[rbw * APAD + kb];
                al[mt][1] = *(const unsigned*)&Alc[(rbw + 8) * APAD + kb];
                al[mt][2] = *(const unsigned*)&Alc[rbw * APAD + kb + 8];
                al[mt][3] = *(const unsigned*)&Alc[(rbw + 8) * APAD + kb + 8];
            }
#pragma unroll
            for (int nt = 0; nt < 8; nt++) {
                int col = wn * 64 + nt * 8 + (lane >> 2);
                unsigned bh0 = Bhc[krow * BPITCH + col];
                unsigned bh1 = Bhc[(krow + 4) * BPITCH + col];
                unsigned bl0 = Blc[krow * BPITCH + col];
                unsigned bl1 = Blc[(krow + 4) * BPITCH + col];
#pragma unroll
                for (int mt = 0; mt < 2; mt++) {
                    mma_bf16(acc[mt][nt], ah[mt], bh0, bh1);
                    mma_bf16(acc[mt][nt], ah[mt], bl0, bl1);
                    mma_bf16(acc[mt][nt], al[mt], bh0, bh1);
                }
            }
        }

        if (more) storeB(cur ^ 1);
        cur ^= 1;
    }
    __syncthreads();

    // ---- epilogue: two 64-col passes through Cs[128][65] ----
#pragma unroll 1
    for (int p = 0; p < 2; p++) {
        if (wn == p) {
#pragma unroll
            for (int mt = 0; mt < 2; mt++)
#pragma unroll
                for (int nt = 0; nt < 8; nt++) {
                    int r = wm * 32 + mt * 16 + (lane >> 2);
                    int cl = nt * 8 + (lane & 3) * 2;
                    Cs[r * 65 + cl]           = acc[mt][nt][0];
                    Cs[r * 65 + cl + 1]       = acc[mt][nt][1];
                    Cs[(r + 8) * 65 + cl]     = acc[mt][nt][2];
                    Cs[(r + 8) * 65 + cl + 1] = acc[mt][nt][3];
                }
        }
        __syncthreads();
        const int lbase = l0 + p * 64;
        if (MODE == 0) {
            int ch0 = m0 >> 1;
#pragma unroll
            for (int i = 0; i < 16; i++) {
                int e = i * 256 + tid;
                int chl = e >> 6, ll = e & 63;
                float av = Cs[(chl * 2) * 65 + ll] + __ldg(&bias[ch0 + chl]);
                float bv = Cs[(chl * 2 + 1) * 65 + ll] + __ldg(&bias[512 + ch0 + chl]);
                float hv = av / (1.f + expf(-bv));
                size_t off = ((size_t)b * 512 + ch0 + chl) * L_ + lbase + ll;
                g_h[off] = hv;
                bf16 hi, lo; split2(hv, hi, lo);
                g_hh[off] = hi; g_hl[off] = lo;
            }
        } else if (MODE == 1) {
#pragma unroll
            for (int i = 0; i < 32; i++) {
                int e = i * 256 + tid;
                int a = e & 127, ll = e >> 7;
                Cs[a * 65 + ll] += __ldg(&bias[m0 + a]) +
                    e1[((size_t)b * L_ + lbase + ll) * 512 + m0 + a];
            }
            __syncthreads();
#pragma unroll
            for (int i = 0; i < 32; i++) {
                int e = i * 256 + tid;
                int a = e & 127, ll = e >> 7;
                float v = Cs[a * 65 + ll];
                bf16 hi, lo; split2(v, hi, lo);
                size_t off = ((size_t)b * L_ + lbase + ll) * 512 + m0 + a;
                g_qh[off] = hi; g_ql[off] = lo;
            }
        } else {
#pragma unroll
            for (int i = 0; i < 32; i++) {
                int e = i * 256 + tid;
                int cl_ = e >> 6, ll = e & 63;
                size_t off = ((size_t)b * 512 + m0 + cl_) * L_ + lbase + ll;
                outp[off] = Cs[cl_ * 65 + ll] + __ldg(&bias[m0 + cl_])
                          + g_h[off] + e1[off];
            }
        }
        __syncthreads();
    }
}

// ---------------------------------------------------------------------------
// Tensor-core attention (unchanged from R8).
// ---------------------------------------------------------------------------
#define SSP 228
#define ATTN_SMEM_BYTES 231424

__global__ __launch_bounds__(256, 1) void attn_tc_kernel(float* __restrict__ attn_out) {
    extern __shared__ __align__(16) unsigned char dynsm[];
    float* ss  = (float*)dynsm;                    // [128][SSP]
    bf16* As_h = (bf16*)(dynsm + 116736);
    bf16* As_l = As_h + 128 * APAD;
    bf16* Bs_h = As_l + 128 * APAD;
    bf16* Bs_l = Bs_h + PP * APAD;
    float* Cs  = (float*)(dynsm + 116736);
    bf16* Bc_h = (bf16*)(dynsm + 173056);
    bf16* Bc_l = Bc_h + 64 * SSP;

    const int b  = blockIdx.y;
    const int l0 = blockIdx.x * 128;
    const int tid = threadIdx.x;
    const int lane = tid & 31, warp = tid >> 5;
    const int wm = warp >> 1, wn = warp & 1;

    // ================= Phase S: score GEMM =================
    float acc[2][14][4];
#pragma unroll
    for (int mt = 0; mt < 2; mt++)
#pragma unroll
        for (int nt = 0; nt < 14; nt++)
#pragma unroll
            for (int j = 0; j < 4; j++) acc[mt][nt][j] = 0.f;

    for (int k0 = 0; k0 < 512; k0 += BK) {
#pragma unroll
        for (int i = 0; i < 8; i++) {
            int u = i * 256 + tid;
            int row = u >> 4, kp = (u & 15) << 1;
            size_t ga = ((size_t)b * L_ + l0 + row) * 512 + k0 + kp;
            *(unsigned*)&As_h[row * APAD + kp] = *(const unsigned*)&g_qh[ga];
            *(unsigned*)&As_l[row * APAD + kp] = *(const unsigned*)&g_ql[ga];
        }
#pragma unroll
        for (int i = 0; i < 14; i++) {
            int u = i * 256 + tid;
            int row = u >> 4, kp = (u & 15) << 1;
            size_t gb = ((size_t)b * PP + row) * 512 + k0 + kp;
            *(unsigned*)&Bs_h[row * APAD + kp] = *(const unsigned*)&g_fTh[gb];
            *(unsigned*)&Bs_l[row * APAD + kp] = *(const unsigned*)&g_fTl[gb];
        }
        __syncthreads();

#pragma unroll
        for (int ks = 0; ks < BK; ks += 16) {
            const int kb = ks + (lane & 3) * 2;
            unsigned ah[2][4], al[2][4];
#pragma unroll
            for (int mt = 0; mt < 2; mt++) {
                int rb = wm * 32 + mt * 16 + (lane >> 2);
                ah[mt][0] = *(unsigned*)&As_h[rb * APAD + kb];
                ah[mt][1] = *(unsigned*)&As_h[(rb + 8) * APAD + kb];
                ah[mt][2] = *(unsigned*)&As_h[rb * APAD + kb + 8];
                ah[mt][3] = *(unsigned*)&As_h[(rb + 8) * APAD + kb + 8];
                al[mt][0] = *(unsigned*)&As_l[rb * APAD + kb];
                al[mt][1] = *(unsigned*)&As_l[(rb + 8) * APAD + kb];
                al[mt][2] = *(unsigned*)&As_l[rb * APAD + kb + 8];
                al[mt][3] = *(unsigned*)&As_l[(rb + 8) * APAD + kb + 8];
            }
#pragma unroll
            for (int nt = 0; nt < 14; nt++) {
                int col = wn * 112 + nt * 8 + (lane >> 2);
                unsigned bh0 = *(unsigned*)&Bs_h[col * APAD + kb];
                unsigned bh1 = *(unsigned*)&Bs_h[col * APAD + kb + 8];
                unsigned bl0 = *(unsigned*)&Bs_l[col * APAD + kb];
                unsigned bl1 = *(unsigned*)&Bs_l[col * APAD + kb + 8];
#pragma unroll
                for (int mt = 0; mt < 2; mt++) {
                    mma_bf16(acc[mt][nt], ah[mt], bh0, bh1);
                    mma_bf16(acc[mt][nt], ah[mt], bl0, bl1);
                    mma_bf16(acc[mt][nt], al[mt], bh0, bh1);
                }
            }
        }
        __syncthreads();
    }

#pragma unroll
    for (int mt = 0; mt < 2; mt++)
#pragma unroll
        for (int nt = 0; nt < 14; nt++) {
            int r = wm * 32 + mt * 16 + (lane >> 2);
            int cl = wn * 112 + nt * 8 + (lane & 3) * 2;
            ss[r * SSP + cl]           = acc[mt][nt][0];
            ss[r * SSP + cl + 1]       = acc[mt][nt][1];
            ss[(r + 8) * SSP + cl]     = acc[mt][nt][2];
            ss[(r + 8) * SSP + cl + 1] = acc[mt][nt][3];
        }
    __syncthreads();

    // ================= Softmax =================
    for (int r = 0; r < 16; r++) {
        int row = warp * 16 + r;
        float v[7];
        float mx = -1e30f;
#pragma unroll
        for (int k = 0; k < 7; k++) {
            int p = lane + 32 * k;
            v[k] = (p < HW) ? ss[row * SSP + p] : -1e30f;
            mx = fmaxf(mx, v[k]);
        }
#pragma unroll
        for (int off = 16; off > 0; off >>= 1)
            mx = fmaxf(mx, __shfl_xor_sync(0xffffffffu, mx, off));
        float s = 0.f;
#pragma unroll
        for (int k = 0; k < 7; k++) {
            int p = lane + 32 * k;
            if (p < HW) { v[k] = expf(v[k] - mx); s += v[k]; }
        }
#pragma unroll
        for (int off = 16; off > 0; off >>= 1)
            s += __shfl_xor_sync(0xffffffffu, s, off);
        float inv = 1.f / s;
        float* ao = attn_out + ((size_t)b * L_ + l0 + row) * HW;
#pragma unroll
        for (int k = 0; k < 7; k++) {
            int p = lane + 32 * k;
            if (p < HW) {
                float a = v[k] * inv;
                ss[row * SSP + p] = a;
                ao[p] = a;
            } else {
                ss[row * SSP + p] = 0.f;
            }
        }
    }
    __syncthreads();

    // ================= Phase C: ctx GEMM =================
#pragma unroll 1
    for (int a0 = 0; a0 < 512; a0 += 64) {
#pragma unroll
        for (int i = 0; i < 28; i++) {
            int u = i * 256 + tid;
            int row = u / 112, pc = (u - row * 112) * 2;
            size_t gb = ((size_t)b * 512 + a0 + row) * PP + pc;
            *(unsigned*)&Bc_h[row * SSP + pc] = *(const unsigned*)&g_fh[gb];
            *(unsigned*)&Bc_l[row * SSP + pc] = *(const unsigned*)&g_fl[gb];
        }
        __syncthreads();

        float ac2[2][4][4];
#pragma unroll
        for (int mt = 0; mt < 2; mt++)
#pragma unroll
            for (int nt = 0; nt < 4; nt++)
#pragma unroll
                for (int j = 0; j < 4; j++) ac2[mt][nt][j] = 0.f;

#pragma unroll 2
        for (int p0 = 0; p0 < PP; p0 += 16) {
            const int kb = p0 + (lane & 3) * 2;
            unsigned ah[2][4], al[2][4];
#pragma unroll
            for (int mt = 0; mt < 2; mt++) {
                int rb = wm * 32 + mt * 16 + (lane >> 2);
#pragma unroll
                for (int f = 0; f < 4; f++) {
                    int rr = rb + ((f & 1) ? 8 : 0);
                    int cc = kb + ((f & 2) ? 8 : 0);
                    float2 v = *(const float2*)&ss[rr * SSP + cc];
                    bf16 h0 = __float2bfloat16(v.x);
                    bf16 h1 = __float2bfloat16(v.y);
                    __nv_bfloat162 hp; hp.x = h0; hp.y = h1;
                    __nv_bfloat162 lp;
                    lp.x = __float2bfloat16(v.x - __bfloat162float(h0));
                    lp.y = __float2bfloat16(v.y - __bfloat162float(h1));
                    ah[mt][f] = *(unsigned*)&hp;
                    al[mt][f] = *(unsigned*)&lp;
                }
            }
#pragma unroll
            for (int nt = 0; nt < 4; nt++) {
                int col = wn * 32 + nt * 8 + (lane >> 2);
                unsigned bh0 = *(unsigned*)&Bc_h[col * SSP + kb];
                unsigned bh1 = *(unsigned*)&Bc_h[col * SSP + kb + 8];
                unsigned bl0 = *(unsigned*)&Bc_l[col * SSP + kb];
                unsigned bl1 = *(unsigned*)&Bc_l[col * SSP + kb + 8];
#pragma unroll
                for (int mt = 0; mt < 2; mt++) {
                    mma_bf16(ac2[mt][nt], ah[mt], bh0, bh1);
                    mma_bf16(ac2[mt][nt], ah[mt], bl0, bl1);
                    mma_bf16(ac2[mt][nt], al[mt], bh0, bh1);
                }
            }
        }

#pragma unroll
        for (int mt = 0; mt < 2; mt++)
#pragma unroll
            for (int nt = 0; nt < 4; nt++) {
                int r = wm * 32 + mt * 16 + (lane >> 2);
                int cl = wn * 32 + nt * 8 + (lane & 3) * 2;
                Cs[r * 65 + cl]           = ac2[mt][nt][0];
                Cs[r * 65 + cl + 1]       = ac2[mt][nt][1];
                Cs[(r + 8) * 65 + cl]     = ac2[mt][nt][2];
                Cs[(r + 8) * 65 + cl + 1] = ac2[mt][nt][3];
            }
        __syncthreads();

#pragma unroll
        for (int i = 0; i < 32; i++) {
            int e = i * 256 + tid;
            int a = e >> 7, l = e & 127;
            float v = Cs[l * 65 + a];
            bf16 hi, lo; split2(v, hi, lo);
            size_t off = ((size_t)b * 512 + a0 + a) * L_ + l0 + l;
            g_cxh[off] = hi; g_cxl[off] = lo;
        }
        __syncthreads();
    }
}

// ---------------------------------------------------------------------------
extern "C" void kernel_launch(void* const* d_in, const int* in_sizes, int n_in,
                              void* d_out, int out_size) {
    (void)in_sizes; (void)n_in; (void)out_size;
    const float* x      = (const float*)d_in[0];
    const float* we     = (const float*)d_in[1];
    const float* img    = (const float*)d_in[2];
    /* d_in[3] prev_attn unused */
    const float* conv_v = (const float*)d_in[4];
    const float* conv_g = (const float*)d_in[5];
    const float* conv_b = (const float*)d_in[6];
    const float* fc1_w  = (const float*)d_in[7];
    const float* fc1_b  = (const float*)d_in[8];
    const float* fc2_w  = (const float*)d_in[9];
    const float* fc2_b  = (const float*)d_in[10];
    float* out = (float*)d_out;

    // passthrough copies
    cudaMemcpyAsync(out + OUT_WE, we, (size_t)B_ * L_ * DW * sizeof(float),
                    cudaMemcpyDeviceToDevice, 0);
    cudaMemcpyAsync(out + OUT_IMG, img, (size_t)B_ * DW * HW * sizeof(float),
                    cudaMemcpyDeviceToDevice, 0);

    // device-symbol addresses for split targets
    void *p_xh, *p_xl, *p_w1h, *p_w1l, *p_w2h, *p_w2l;
    cudaGetSymbolAddress(&p_xh, g_xh);
    cudaGetSymbolAddress(&p_xl, g_xl);
    cudaGetSymbolAddress(&p_w1h, g_w1h);
    cudaGetSymbolAddress(&p_w1l, g_w1l);
    cudaGetSymbolAddress(&p_w2h, g_w2h);
    cudaGetSymbolAddress(&p_w2l, g_w2l);

    // prep
    wnorm_kernel<<<COUT, 256>>>(conv_v, conv_g);
    convw_split_kernel<<<COUT, 256>>>();
    split_kernel<<<2048, 256>>>(x, (bf16*)p_xh, (bf16*)p_xl, B_ * CIN * L_);
    split_kernel<<<256, 256>>>(fc1_w, (bf16*)p_w1h, (bf16*)p_w1l, DW * DW);
    split_kernel<<<256, 256>>>(fc2_w, (bf16*)p_w2h, (bf16*)p_w2l, DW * DW);
    featT_kernel<<<dim3(PP / 32, 512 / 32, B_), dim3(32, 8)>>>(img);
    featpad_kernel<<<(B_ * 512 * PP + 255) / 256, 256>>>(img);

    // opt-in dynamic smem for gemm kernels
    cudaFuncSetAttribute(gemm_kernel<0>, cudaFuncAttributeMaxDynamicSharedMemorySize, GEMM_SMEM);
    cudaFuncSetAttribute(gemm_kernel<1>, cudaFuncAttributeMaxDynamicSharedMemorySize, GEMM_SMEM);
    cudaFuncSetAttribute(gemm_kernel<2>, cudaFuncAttributeMaxDynamicSharedMemorySize, GEMM_SMEM);

    // conv + GLU  (M=1024 interleaved, N=1024, K=2560)
    gemm_kernel<0><<<dim3(L_ / BN, COUT / BM, B_), 256, GEMM_SMEM>>>(conv_b, nullptr, nullptr);
    // fc1 (M=512, N=1024, K=512) -> q bf16 (b,l,a)
    gemm_kernel<1><<<dim3(L_ / BN, DW / BM, B_), 256, GEMM_SMEM>>>(fc1_b, we, nullptr);

    // tensor-core attention
    cudaFuncSetAttribute(attn_tc_kernel, cudaFuncAttributeMaxDynamicSharedMemorySize,
                         ATTN_SMEM_BYTES);
    attn_tc_kernel<<<dim3(L_ / 128, B_), 256, ATTN_SMEM_BYTES>>>(out + OUT_ATTN);

    // fc2 + residuals (M=512, N=1024, K=512)
    gemm_kernel<2><<<dim3(L_ / BN, DW / BM, B_), 256, GEMM_SMEM>>>(fc2_b, x, out);
}

// round 10
// speedup vs baseline: 1.8640x; 1.8640x over previous
#include <cuda_runtime.h>
#include <cuda_bf16.h>
#include <math.h>

// Problem constants
#define B_  16
#define CIN 512
#define L_  1024
#define COUT 1024
#define K_  5
#define DW  512
#define HW  196
#define KCONV (CIN * K_)   // 2560
#define PP  224            // padded p dimension

// Output layout (concatenated tuple): out, word_embed, img_conv, attn
#define OUT_WE   8388608u
#define OUT_IMG  16777216u
#define OUT_ATTN 18382848u

typedef __nv_bfloat16 bf16;

// ---------------------------------------------------------------------------
// Scratch (device globals; allocation-free rule)
// ---------------------------------------------------------------------------
__device__ float g_w[COUT * KCONV];            // normalized conv weights (co, c, t)
__device__ float g_h[B_ * DW * L_];            // GLU output fp32 (b, ch, l)
__device__ bf16 g_xTh[B_ * L_ * CIN], g_xTl[B_ * L_ * CIN];   // x^T split (b, l, c)
__device__ bf16 g_cwp[8 * 80 * 2 * 5120];      // conv W packed tiles [mb][kc][plane][128][40]
__device__ bf16 g_w1p[4 * 16 * 2 * 5120];      // fc1 W packed tiles
__device__ bf16 g_w2p[4 * 16 * 2 * 5120];      // fc2 W packed tiles
__device__ bf16 g_hTh[B_ * L_ * DW], g_hTl[B_ * L_ * DW];     // h split (b, l, c)
__device__ bf16 g_qh[B_ * L_ * DW],  g_ql[B_ * L_ * DW];      // q split (b, l, a)
__device__ bf16 g_cxh[B_ * L_ * DW], g_cxl[B_ * L_ * DW];     // ctx split (b, l, a)
__device__ bf16 g_fTh[B_ * PP * DW], g_fTl[B_ * PP * DW];     // feat^T split (b, p, a)
__device__ bf16 g_fh[B_ * DW * PP],  g_fl[B_ * DW * PP];      // feat split (b, a, p)

__device__ __forceinline__ void split2(float v, bf16& h, bf16& l) {
    h = __float2bfloat16(v);
    l = __float2bfloat16(v - __bfloat162float(h));
}

// ---- async copy primitives ----
__device__ __forceinline__ void cp16(void* dst, const void* src) {
    unsigned d = (unsigned)__cvta_generic_to_shared(dst);
    asm volatile("cp.async.cg.shared.global [%0], [%1], 16;\n" :: "r"(d), "l"(src));
}
#define CP_COMMIT() asm volatile("cp.async.commit_group;\n")
#define CP_WAIT0()  asm volatile("cp.async.wait_group 0;\n")
#define CP_WAIT1()  asm volatile("cp.async.wait_group 1;\n")

#define MBAR_INIT(addr, cnt) \
    asm volatile("mbarrier.init.shared.b64 [%0], %1;" :: "r"(addr), "r"(cnt) : "memory")
#define MBAR_EXPECT(addr, tx) \
    asm volatile("mbarrier.arrive.expect_tx.shared.b64 _, [%0], %1;" :: "r"(addr), "r"(tx) : "memory")

__device__ __forceinline__ void mbar_wait(unsigned mbar, unsigned parity) {
    asm volatile(
        "{\n\t.reg .pred P;\n\t"
        "W_%=:\n\t"
        "mbarrier.try_wait.parity.acquire.cta.shared::cta.b64 P, [%0], %1;\n\t"
        "@!P bra W_%=;\n\t}"
        :: "r"(mbar), "r"(parity) : "memory");
}

__device__ __forceinline__ void bulk_g2s(unsigned dst_smem, const void* src,
                                         unsigned bytes, unsigned mbar) {
    asm volatile(
        "cp.async.bulk.shared::cluster.global.mbarrier::complete_tx::bytes "
        "[%0], [%1], %2, [%3];"
        :: "r"(dst_smem), "l"(src), "r"(bytes), "r"(mbar) : "memory");
}

// ---------------------------------------------------------------------------
// Prep kernels
// ---------------------------------------------------------------------------
__global__ void wnorm_kernel(const float* __restrict__ v,
                             const float* __restrict__ g) {
    int co = blockIdx.x;
    const float* vr = v + (size_t)co * KCONV;
    float s = 0.f;
    for (int i = threadIdx.x; i < KCONV; i += 256) { float t = vr[i]; s += t * t; }
    __shared__ float red[256];
    red[threadIdx.x] = s;
    __syncthreads();
    for (int st = 128; st > 0; st >>= 1) {
        if (threadIdx.x < st) red[threadIdx.x] += red[threadIdx.x + st];
        __syncthreads();
    }
    float scale = g[co] / sqrtf(red[0]);
    float* wr = g_w + (size_t)co * KCONV;
    for (int i = threadIdx.x; i < KCONV; i += 256) wr[i] = scale * vr[i];
}

// pack conv weights: tile (mb, kc=t*16+ci): [128 m][40 pitch], kcol -> c=ci*32+kcol
__global__ void pack_conv_kernel() {
    const int kc = blockIdx.x, mb = blockIdx.y;
    const int t = kc >> 4, ci = kc & 15;
    bf16* dst = g_cwp + ((size_t)(mb * 80 + kc)) * 2 * 5120;
    for (int idx = threadIdx.x; idx < 128 * 32; idx += 256) {
        int row = idx >> 5, kcol = idx & 31;
        int m = mb * 128 + row;
        int co = (m & 1) ? (512 + (m >> 1)) : (m >> 1);
        int c = ci * 32 + kcol;
        float v = g_w[(size_t)co * KCONV + c * K_ + t];
        bf16 hi, lo; split2(v, hi, lo);
        dst[row * 40 + kcol] = hi;
        dst[5120 + row * 40 + kcol] = lo;
    }
}

// pack fc weights: W [m=512][k=512] row-major -> tiles [mb 4][kc 16][plane][128][40]
__global__ void pack_fc_kernel(const float* __restrict__ W, bf16* __restrict__ dstall) {
    const int kc = blockIdx.x, mb = blockIdx.y;
    bf16* dst = dstall + ((size_t)(mb * 16 + kc)) * 2 * 5120;
    for (int idx = threadIdx.x; idx < 128 * 32; idx += 256) {
        int row = idx >> 5, kcol = idx & 31;
        float v = W[(size_t)(mb * 128 + row) * 512 + kc * 32 + kcol];
        bf16 hi, lo; split2(v, hi, lo);
        dst[row * 40 + kcol] = hi;
        dst[5120 + row * 40 + kcol] = lo;
    }
}

// x (b,c,l) -> xT split (b,l,c)
__global__ void xT_kernel(const float* __restrict__ x) {
    __shared__ float t[32][33];
    const int b = blockIdx.z, l0 = blockIdx.x * 32, c0 = blockIdx.y * 32;
    const int tx = threadIdx.x, ty0 = threadIdx.y;
#pragma unroll
    for (int j = 0; j < 4; j++) {
        int ty = ty0 + j * 8;
        t[ty][tx] = x[((size_t)b * CIN + c0 + ty) * L_ + l0 + tx];
    }
    __syncthreads();
#pragma unroll
    for (int j = 0; j < 4; j++) {
        int ty = ty0 + j * 8;
        float v = t[tx][ty];   // element (c0+tx, l0+ty)
        bf16 hi, lo; split2(v, hi, lo);
        size_t off = ((size_t)b * L_ + l0 + ty) * 512 + c0 + tx;
        g_xTh[off] = hi; g_xTl[off] = lo;
    }
}

// feat^T split (b, p, a); p>=196 rows zero.
__global__ void featT_kernel(const float* __restrict__ img) {
    __shared__ float t[32][33];
    const int b = blockIdx.z, p0 = blockIdx.x * 32, a0 = blockIdx.y * 32;
    const int tx = threadIdx.x, ty0 = threadIdx.y;
#pragma unroll
    for (int j = 0; j < 4; j++) {
        int ty = ty0 + j * 8;
        int a = a0 + ty, p = p0 + tx;
        t[ty][tx] = (p < HW) ? img[((size_t)b * 512 + a) * HW + p] : 0.f;
    }
    __syncthreads();
#pragma unroll
    for (int j = 0; j < 4; j++) {
        int ty = ty0 + j * 8;
        float v = t[tx][ty];
        bf16 hi, lo; split2(v, hi, lo);
        size_t off = ((size_t)b * PP + p0 + ty) * 512 + a0 + tx;
        g_fTh[off] = hi; g_fTl[off] = lo;
    }
}

__global__ void featpad_kernel(const float* __restrict__ img) {
    int idx = blockIdx.x * 256 + threadIdx.x;
    if (idx >= B_ * 512 * PP) return;
    int p = idx % PP, ba = idx / PP;
    float v = (p < HW) ? img[(size_t)ba * HW + p] : 0.f;
    bf16 hi, lo; split2(v, hi, lo);
    g_fh[idx] = hi; g_fl[idx] = lo;
}

// ---------------------------------------------------------------------------
// MMA helper
// ---------------------------------------------------------------------------
__device__ __forceinline__ void mma_bf16(float* c, const unsigned* a,
                                         unsigned b0, unsigned b1) {
    asm volatile(
        "mma.sync.aligned.m16n8k16.row.col.f32.bf16.bf16.f32 "
        "{%0,%1,%2,%3}, {%4,%5,%6,%7}, {%8,%9}, {%0,%1,%2,%3};\n"
        : "+f"(c[0]), "+f"(c[1]), "+f"(c[2]), "+f"(c[3])
        : "r"(a[0]), "r"(a[1]), "r"(a[2]), "r"(a[3]), "r"(b0), "r"(b1));
}

#define APAD 40
#define BK 32

// ---------------------------------------------------------------------------
// Conv GEMM: c-chunk (16) x t (5) loop, bulk-staged packed A, cp.async B (xT).
//   smem: A stages 2x20480 @0 ; B stages 2x21760 @40960 ; mbar[2] @84480
// ---------------------------------------------------------------------------
#define CONV_A_STAGE 20480
#define CONV_B_OFF   40960
#define CONV_B_STAGE 21760
#define CONV_MBAR    84480
#define CONV_SMEM    84608

__global__ __launch_bounds__(256, 2) void conv_gemm(const float* __restrict__ bias) {
    extern __shared__ __align__(16) unsigned char dynsm[];
    const int b = blockIdx.z, mb = blockIdx.y, l0 = blockIdx.x * 128;
    const int tid = threadIdx.x;
    const int lane = tid & 31, warp = tid >> 5;
    const int wm = warp >> 1, wn = warp & 1;

    unsigned smem_base = (unsigned)__cvta_generic_to_shared(dynsm);
    unsigned mbar0 = smem_base + CONV_MBAR, mbar1 = mbar0 + 8;
    if (tid == 0) { MBAR_INIT(mbar0, 1); MBAR_INIT(mbar1, 1); }
    __syncthreads();

    float acc[2][8][4];
#pragma unroll
    for (int mt = 0; mt < 2; mt++)
#pragma unroll
        for (int nt = 0; nt < 8; nt++)
#pragma unroll
            for (int j = 0; j < 4; j++) acc[mt][nt][j] = 0.f;

    auto issueA = [&](int s, int kc) {
        if (tid == 0) {
            unsigned mbx = s ? mbar1 : mbar0;
            MBAR_EXPECT(mbx, CONV_A_STAGE);
            const char* src = (const char*)g_cwp + ((size_t)(mb * 80 + kc)) * CONV_A_STAGE;
            bulk_g2s(smem_base + s * CONV_A_STAGE, src, CONV_A_STAGE, mbx);
        }
    };
    auto issueB = [&](int sb, int ci) {
        int c0 = ci * 32;
        unsigned char* dst0 = dynsm + CONV_B_OFF + sb * CONV_B_STAGE;
#pragma unroll
        for (int ii = 0; ii < 5; ii++) {
            int u = ii * 256 + tid;
            if (u < 1056) {
                int plane = (u >= 528) ? 1 : 0;
                int v = u - plane * 528;
                int r = v >> 2, j = v & 3;
                if (!(l0 == 0 && r < 4)) {
                    const bf16* src = (plane ? g_xTl : g_xTh) +
                        ((size_t)b * L_ + l0 - 4 + r) * 512 + c0 + j * 8;
                    cp16(dst0 + plane * 10880 + r * 80 + j * 16, src);
                }
            }
        }
        if (l0 == 0 && tid < 160) {
            int plane = tid / 80, v = tid % 80, r = v / 20, w = v % 20;
            *(unsigned*)(dst0 + plane * 10880 + r * 80 + w * 4) = 0u;
        }
    };

    // prologue
    issueB(0, 0);
    CP_COMMIT();
    issueA(0, 0);
    int ph0 = 0, ph1 = 0;

    for (int i = 0; i < 80; i++) {
        const int ci = i / 5, t = i - ci * 5, s = i & 1;
        if (i + 1 < 80) {
            int ni = i + 1, nci = ni / 5, nt = ni - nci * 5;
            issueA(ni & 1, nt * 16 + nci);
            if (nt == 0) { issueB(nci & 1, nci); CP_COMMIT(); }
        }
        if (s == 0) { mbar_wait(mbar0, ph0); ph0 ^= 1; }
        else        { mbar_wait(mbar1, ph1); ph1 ^= 1; }
        if (t == 0) CP_WAIT0();
        __syncthreads();

        const bf16* Ah = (const bf16*)(dynsm + s * CONV_A_STAGE);
        const bf16* Al = Ah + 5120;
        const bf16* Bh = (const bf16*)(dynsm + CONV_B_OFF + (ci & 1) * CONV_B_STAGE);
        const bf16* Bl = Bh + 5440;

#pragma unroll
        for (int ks = 0; ks < 2; ks++) {
            const int kb = ks * 16 + (lane & 3) * 2;
            unsigned ah[2][4], al[2][4];
#pragma unroll
            for (int mt = 0; mt < 2; mt++) {
                int rbw = wm * 32 + mt * 16 + (lane >> 2);
                ah[mt][0] = *(const unsigned*)&Ah[rbw * APAD + kb];
                ah[mt][1] = *(const unsigned*)&Ah[(rbw + 8) * APAD + kb];
                ah[mt][2] = *(const unsigned*)&Ah[rbw * APAD + kb + 8];
                ah[mt][3] = *(const unsigned*)&Ah[(rbw + 8) * APAD + kb + 8];
                al[mt][0] = *(const unsigned*)&Al[rbw * APAD + kb];
                al[mt][1] = *(const unsigned*)&Al[(rbw + 8) * APAD + kb];
                al[mt][2] = *(const unsigned*)&Al[rbw * APAD + kb + 8];
                al[mt][3] = *(const unsigned*)&Al[(rbw + 8) * APAD + kb + 8];
            }
#pragma unroll
            for (int nt = 0; nt < 8; nt++) {
                int row = wn * 64 + nt * 8 + (lane >> 2) + t;  // col + t shift
                unsigned bh0 = *(const unsigned*)&Bh[row * APAD + kb];
                unsigned bh1 = *(const unsigned*)&Bh[row * APAD + kb + 8];
                unsigned bl0 = *(const unsigned*)&Bl[row * APAD + kb];
                unsigned bl1 = *(const unsigned*)&Bl[row * APAD + kb + 8];
#pragma unroll
                for (int mt = 0; mt < 2; mt++) {
                    mma_bf16(acc[mt][nt], ah[mt], bh0, bh1);
                    mma_bf16(acc[mt][nt], ah[mt], bl0, bl1);
                    mma_bf16(acc[mt][nt], al[mt], bh0, bh1);
                }
            }
        }
        __syncthreads();
    }

    // ---- epilogue: two 64-col passes through Cs[128][65] ----
    float* Cs = (float*)dynsm;
    const int ch0 = (mb * 128) >> 1;
#pragma unroll 1
    for (int p = 0; p < 2; p++) {
        if (wn == p) {
#pragma unroll
            for (int mt = 0; mt < 2; mt++)
#pragma unroll
                for (int nt = 0; nt < 8; nt++) {
                    int r = wm * 32 + mt * 16 + (lane >> 2);
                    int cl = nt * 8 + (lane & 3) * 2;
                    Cs[r * 65 + cl]           = acc[mt][nt][0];
                    Cs[r * 65 + cl + 1]       = acc[mt][nt][1];
                    Cs[(r + 8) * 65 + cl]     = acc[mt][nt][2];
                    Cs[(r + 8) * 65 + cl + 1] = acc[mt][nt][3];
                }
        }
        __syncthreads();
        const int lbase = l0 + p * 64;
        // GLU + fp32 h write (l-fast), stash hv into Cs a-half rows
#pragma unroll
        for (int i = 0; i < 16; i++) {
            int e = i * 256 + tid;
            int chl = e >> 6, ll = e & 63;
            float av = Cs[(chl * 2) * 65 + ll] + __ldg(&bias[ch0 + chl]);
            float bv = Cs[(chl * 2 + 1) * 65 + ll] + __ldg(&bias[512 + ch0 + chl]);
            float hv = av / (1.f + expf(-bv));
            g_h[((size_t)b * 512 + ch0 + chl) * L_ + lbase + ll] = hv;
            Cs[(chl * 2) * 65 + ll] = hv;
        }
        __syncthreads();
        // transposed bf16 split write (c-fast) -> hT (b,l,c)
#pragma unroll
        for (int i = 0; i < 16; i++) {
            int e = i * 256 + tid;
            int chl = e & 63, ll = e >> 6;
            float hv = Cs[(chl * 2) * 65 + ll];
            bf16 hi, lo; split2(hv, hi, lo);
            size_t off = ((size_t)b * L_ + lbase + ll) * 512 + ch0 + chl;
            g_hTh[off] = hi; g_hTl[off] = lo;
        }
        __syncthreads();
    }
}

// ---------------------------------------------------------------------------
// fc GEMM (MODE 1: fc1, MODE 2: fc2). Bulk-staged packed A, cp.async B.
//   smem: A stages 2x20480 @0 ; B stages 2x20480 @40960 ; mbar[2] @81920
// ---------------------------------------------------------------------------
#define FC_A_STAGE 20480
#define FC_B_OFF   40960
#define FC_B_STAGE 20480
#define FC_MBAR    81920
#define FC_SMEM    82048

template <int MODE>
__global__ __launch_bounds__(256, 2) void fc_gemm(
    const float* __restrict__ bias, const float* __restrict__ e1,
    float* __restrict__ outp) {
    extern __shared__ __align__(16) unsigned char dynsm[];
    const int b = blockIdx.z, mb = blockIdx.y, l0 = blockIdx.x * 128;
    const int m0 = mb * 128;
    const int tid = threadIdx.x;
    const int lane = tid & 31, warp = tid >> 5;
    const int wm = warp >> 1, wn = warp & 1;

    const bf16* Wp  = (MODE == 1) ? g_w1p : g_w2p;
    const bf16* Bgh = (MODE == 1) ? g_hTh : g_cxh;   // (b, l, k)
    const bf16* Bgl = (MODE == 1) ? g_hTl : g_cxl;

    unsigned smem_base = (unsigned)__cvta_generic_to_shared(dynsm);
    unsigned mbar0 = smem_base + FC_MBAR, mbar1 = mbar0 + 8;
    if (tid == 0) { MBAR_INIT(mbar0, 1); MBAR_INIT(mbar1, 1); }
    __syncthreads();

    float acc[2][8][4];
#pragma unroll
    for (int mt = 0; mt < 2; mt++)
#pragma unroll
        for (int nt = 0; nt < 8; nt++)
#pragma unroll
            for (int j = 0; j < 4; j++) acc[mt][nt][j] = 0.f;

    auto issueA = [&](int s, int kc) {
        if (tid == 0) {
            unsigned mbx = s ? mbar1 : mbar0;
            MBAR_EXPECT(mbx, FC_A_STAGE);
            const char* src = (const char*)Wp + ((size_t)(mb * 16 + kc)) * FC_A_STAGE;
            bulk_g2s(smem_base + s * FC_A_STAGE, src, FC_A_STAGE, mbx);
        }
    };
    auto issueB = [&](int s, int kc) {
        unsigned char* dst0 = dynsm + FC_B_OFF + s * FC_B_STAGE;
#pragma unroll
        for (int ii = 0; ii < 4; ii++) {
            int u = ii * 256 + tid;
            int plane = u >> 9, v = u & 511;
            int r = v >> 2, j = v & 3;
            const bf16* src = (plane ? Bgl : Bgh) +
                ((size_t)b * L_ + l0 + r) * 512 + kc * 32 + j * 8;
            cp16(dst0 + plane * 10240 + r * 80 + j * 16, src);
        }
    };

    issueA(0, 0);
    issueB(0, 0);
    CP_COMMIT();
    int ph0 = 0, ph1 = 0;

    for (int i = 0; i < 16; i++) {
        const int s = i & 1;
        if (i < 15) {
            issueA(s ^ 1, i + 1);
            issueB(s ^ 1, i + 1);
            CP_COMMIT();
        }
        if (s == 0) { mbar_wait(mbar0, ph0); ph0 ^= 1; }
        else        { mbar_wait(mbar1, ph1); ph1 ^= 1; }
        if (i < 15) CP_WAIT1(); else CP_WAIT0();
        __syncthreads();

        const bf16* Ah = (const bf16*)(dynsm + s * FC_A_STAGE);
        const bf16* Al = Ah + 5120;
        const bf16* Bh = (const bf16*)(dynsm + FC_B_OFF + s * FC_B_STAGE);
        const bf16* Bl = Bh + 5120;

#pragma unroll
        for (int ks = 0; ks < 2; ks++) {
            const int kb = ks * 16 + (lane & 3) * 2;
            unsigned ah[2][4], al[2][4];
#pragma unroll
            for (int mt = 0; mt < 2; mt++) {
                int rbw = wm * 32 + mt * 16 + (lane >> 2);
                ah[mt][0] = *(const unsigned*)&Ah[rbw * APAD + kb];
                ah[mt][1] = *(const unsigned*)&Ah[(rbw + 8) * APAD + kb];
                ah[mt][2] = *(const unsigned*)&Ah[rbw * APAD + kb + 8];
                ah[mt][3] = *(const unsigned*)&Ah[(rbw + 8) * APAD + kb + 8];
                al[mt][0] = *(const unsigned*)&Al[rbw * APAD + kb];
                al[mt][1] = *(const unsigned*)&Al[(rbw + 8) * APAD + kb];
                al[mt][2] = *(const unsigned*)&Al[rbw * APAD + kb + 8];
                al[mt][3] = *(const unsigned*)&Al[(rbw + 8) * APAD + kb + 8];
            }
#pragma unroll
            for (int nt = 0; nt < 8; nt++) {
                int col = wn * 64 + nt * 8 + (lane >> 2);
                unsigned bh0 = *(const unsigned*)&Bh[col * APAD + kb];
                unsigned bh1 = *(const unsigned*)&Bh[col * APAD + kb + 8];
                unsigned bl0 = *(const unsigned*)&Bl[col * APAD + kb];
                unsigned bl1 = *(const unsigned*)&Bl[col * APAD + kb + 8];
#pragma unroll
                for (int mt = 0; mt < 2; mt++) {
                    mma_bf16(acc[mt][nt], ah[mt], bh0, bh1);
                    mma_bf16(acc[mt][nt], ah[mt], bl0, bl1);
                    mma_bf16(acc[mt][nt], al[mt], bh0, bh1);
                }
            }
        }
        __syncthreads();
    }

    // ---- epilogue ----
    float* Cs = (float*)dynsm;
#pragma unroll 1
    for (int p = 0; p < 2; p++) {
        if (wn == p) {
#pragma unroll
            for (int mt = 0; mt < 2; mt++)
#pragma unroll
                for (int nt = 0; nt < 8; nt++) {
                    int r = wm * 32 + mt * 16 + (lane >> 2);
                    int cl = nt * 8 + (lane & 3) * 2;
                    Cs[r * 65 + cl]           = acc[mt][nt][0];
                    Cs[r * 65 + cl + 1]       = acc[mt][nt][1];
                    Cs[(r + 8) * 65 + cl]     = acc[mt][nt][2];
                    Cs[(r + 8) * 65 + cl + 1] = acc[mt][nt][3];
                }
        }
        __syncthreads();
        const int lbase = l0 + p * 64;
        if (MODE == 1) {
#pragma unroll
            for (int i = 0; i < 32; i++) {
                int e = i * 256 + tid;
                int a = e & 127, ll = e >> 7;
                Cs[a * 65 + ll] += __ldg(&bias[m0 + a]) +
                    e1[((size_t)b * L_ + lbase + ll) * 512 + m0 + a];
            }
            __syncthreads();
#pragma unroll
            for (int i = 0; i < 32; i++) {
                int e = i * 256 + tid;
                int a = e & 127, ll = e >> 7;
                float v = Cs[a * 65 + ll];
                bf16 hi, lo; split2(v, hi, lo);
                size_t off = ((size_t)b * L_ + lbase + ll) * 512 + m0 + a;
                g_qh[off] = hi; g_ql[off] = lo;
            }
        } else {
#pragma unroll
            for (int i = 0; i < 32; i++) {
                int e = i * 256 + tid;
                int cl_ = e >> 6, ll = e & 63;
                size_t off = ((size_t)b * 512 + m0 + cl_) * L_ + lbase + ll;
                outp[off] = Cs[cl_ * 65 + ll] + __ldg(&bias[m0 + cl_])
                          + g_h[off] + e1[off];
            }
        }
        __syncthreads();
    }
}

// ---------------------------------------------------------------------------
// Tensor-core attention (R8), ctx now emitted (b, l, a).
// ---------------------------------------------------------------------------
#define SSP 228
#define ATTN_SMEM_BYTES 231424

__global__ __launch_bounds__(256, 1) void attn_tc_kernel(float* __restrict__ attn_out) {
    extern __shared__ __align__(16) unsigned char dynsm[];
    float* ss  = (float*)dynsm;                    // [128][SSP]
    bf16* As_h = (bf16*)(dynsm + 116736);
    bf16* As_l = As_h + 128 * APAD;
    bf16* Bs_h = As_l + 128 * APAD;
    bf16* Bs_l = Bs_h + PP * APAD;
    float* Cs  = (float*)(dynsm + 116736);
    bf16* Bc_h = (bf16*)(dynsm + 173056);
    bf16* Bc_l = Bc_h + 64 * SSP;

    const int b  = blockIdx.y;
    const int l0 = blockIdx.x * 128;
    const int tid = threadIdx.x;
    const int lane = tid & 31, warp = tid >> 5;
    const int wm = warp >> 1, wn = warp & 1;

    // ================= Phase S: score GEMM =================
    float acc[2][14][4];
#pragma unroll
    for (int mt = 0; mt < 2; mt++)
#pragma unroll
        for (int nt = 0; nt < 14; nt++)
#pragma unroll
            for (int j = 0; j < 4; j++) acc[mt][nt][j] = 0.f;

    for (int k0 = 0; k0 < 512; k0 += BK) {
#pragma unroll
        for (int i = 0; i < 8; i++) {
            int u = i * 256 + tid;
            int row = u >> 4, kp = (u & 15) << 1;
            size_t ga = ((size_t)b * L_ + l0 + row) * 512 + k0 + kp;
            *(unsigned*)&As_h[row * APAD + kp] = *(const unsigned*)&g_qh[ga];
            *(unsigned*)&As_l[row * APAD + kp] = *(const unsigned*)&g_ql[ga];
        }
#pragma unroll
        for (int i = 0; i < 14; i++) {
            int u = i * 256 + tid;
            int row = u >> 4, kp = (u & 15) << 1;
            size_t gb = ((size_t)b * PP + row) * 512 + k0 + kp;
            *(unsigned*)&Bs_h[row * APAD + kp] = *(const unsigned*)&g_fTh[gb];
            *(unsigned*)&Bs_l[row * APAD + kp] = *(const unsigned*)&g_fTl[gb];
        }
        __syncthreads();

#pragma unroll
        for (int ks = 0; ks < BK; ks += 16) {
            const int kb = ks + (lane & 3) * 2;
            unsigned ah[2][4], al[2][4];
#pragma unroll
            for (int mt = 0; mt < 2; mt++) {
                int rb = wm * 32 + mt * 16 + (lane >> 2);
                ah[mt][0] = *(unsigned*)&As_h[rb * APAD + kb];
                ah[mt][1] = *(unsigned*)&As_h[(rb + 8) * APAD + kb];
                ah[mt][2] = *(unsigned*)&As_h[rb * APAD + kb + 8];
                ah[mt][3] = *(unsigned*)&As_h[(rb + 8) * APAD + kb + 8];
                al[mt][0] = *(unsigned*)&As_l[rb * APAD + kb];
                al[mt][1] = *(unsigned*)&As_l[(rb + 8) * APAD + kb];
                al[mt][2] = *(unsigned*)&As_l[rb * APAD + kb + 8];
                al[mt][3] = *(unsigned*)&As_l[(rb + 8) * APAD + kb + 8];
            }
#pragma unroll
            for (int nt = 0; nt < 14; nt++) {
                int col = wn * 112 + nt * 8 + (lane >> 2);
                unsigned bh0 = *(unsigned*)&Bs_h[col * APAD + kb];
                unsigned bh1 = *(unsigned*)&Bs_h[col * APAD + kb + 8];
                unsigned bl0 = *(unsigned*)&Bs_l[col * APAD + kb];
                unsigned bl1 = *(unsigned*)&Bs_l[col * APAD + kb + 8];
#pragma unroll
                for (int mt = 0; mt < 2; mt++) {
                    mma_bf16(acc[mt][nt], ah[mt], bh0, bh1);
                    mma_bf16(acc[mt][nt], ah[mt], bl0, bl1);
                    mma_bf16(acc[mt][nt], al[mt], bh0, bh1);
                }
            }
        }
        __syncthreads();
    }

#pragma unroll
    for (int mt = 0; mt < 2; mt++)
#pragma unroll
        for (int nt = 0; nt < 14; nt++) {
            int r = wm * 32 + mt * 16 + (lane >> 2);
            int cl = wn * 112 + nt * 8 + (lane & 3) * 2;
            ss[r * SSP + cl]           = acc[mt][nt][0];
            ss[r * SSP + cl + 1]       = acc[mt][nt][1];
            ss[(r + 8) * SSP + cl]     = acc[mt][nt][2];
            ss[(r + 8) * SSP + cl + 1] = acc[mt][nt][3];
        }
    __syncthreads();

    // ================= Softmax =================
    for (int r = 0; r < 16; r++) {
        int row = warp * 16 + r;
        float v[7];
        float mx = -1e30f;
#pragma unroll
        for (int k = 0; k < 7; k++) {
            int p = lane + 32 * k;
            v[k] = (p < HW) ? ss[row * SSP + p] : -1e30f;
            mx = fmaxf(mx, v[k]);
        }
#pragma unroll
        for (int off = 16; off > 0; off >>= 1)
            mx = fmaxf(mx, __shfl_xor_sync(0xffffffffu, mx, off));
        float s = 0.f;
#pragma unroll
        for (int k = 0; k < 7; k++) {
            int p = lane + 32 * k;
            if (p < HW) { v[k] = expf(v[k] - mx); s += v[k]; }
        }
#pragma unroll
        for (int off = 16; off > 0; off >>= 1)
            s += __shfl_xor_sync(0xffffffffu, s, off);
        float inv = 1.f / s;
        float* ao = attn_out + ((size_t)b * L_ + l0 + row) * HW;
#pragma unroll
        for (int k = 0; k < 7; k++) {
            int p = lane + 32 * k;
            if (p < HW) {
                float a = v[k] * inv;
                ss[row * SSP + p] = a;
                ao[p] = a;
            } else {
                ss[row * SSP + p] = 0.f;
            }
        }
    }
    __syncthreads();

    // ================= Phase C: ctx GEMM =================
#pragma unroll 1
    for (int a0 = 0; a0 < 512; a0 += 64) {
#pragma unroll
        for (int i = 0; i < 28; i++) {
            int u = i * 256 + tid;
            int row = u / 112, pc = (u - row * 112) * 2;
            size_t gb = ((size_t)b * 512 + a0 + row) * PP + pc;
            *(unsigned*)&Bc_h[row * SSP + pc] = *(const unsigned*)&g_fh[gb];
            *(unsigned*)&Bc_l[row * SSP + pc] = *(const unsigned*)&g_fl[gb];
        }
        __syncthreads();

        float ac2[2][4][4];
#pragma unroll
        for (int mt = 0; mt < 2; mt++)
#pragma unroll
            for (int nt = 0; nt < 4; nt++)
#pragma unroll
                for (int j = 0; j < 4; j++) ac2[mt][nt][j] = 0.f;

#pragma unroll 2
        for (int p0 = 0; p0 < PP; p0 += 16) {
            const int kb = p0 + (lane & 3) * 2;
            unsigned ah[2][4], al[2][4];
#pragma unroll
            for (int mt = 0; mt < 2; mt++) {
                int rb = wm * 32 + mt * 16 + (lane >> 2);
#pragma unroll
                for (int f = 0; f < 4; f++) {
                    int rr = rb + ((f & 1) ? 8 : 0);
                    int cc = kb + ((f & 2) ? 8 : 0);
                    float2 v = *(const float2*)&ss[rr * SSP + cc];
                    bf16 h0 = __float2bfloat16(v.x);
                    bf16 h1 = __float2bfloat16(v.y);
                    __nv_bfloat162 hp; hp.x = h0; hp.y = h1;
                    __nv_bfloat162 lp;
                    lp.x = __float2bfloat16(v.x - __bfloat162float(h0));
                    lp.y = __float2bfloat16(v.y - __bfloat162float(h1));
                    ah[mt][f] = *(unsigned*)&hp;
                    al[mt][f] = *(unsigned*)&lp;
                }
            }
#pragma unroll
            for (int nt = 0; nt < 4; nt++) {
                int col = wn * 32 + nt * 8 + (lane >> 2);
                unsigned bh0 = *(unsigned*)&Bc_h[col * SSP + kb];
                unsigned bh1 = *(unsigned*)&Bc_h[col * SSP + kb + 8];
                unsigned bl0 = *(unsigned*)&Bc_l[col * SSP + kb];
                unsigned bl1 = *(unsigned*)&Bc_l[col * SSP + kb + 8];
#pragma unroll
                for (int mt = 0; mt < 2; mt++) {
                    mma_bf16(ac2[mt][nt], ah[mt], bh0, bh1);
                    mma_bf16(ac2[mt][nt], ah[mt], bl0, bl1);
                    mma_bf16(ac2[mt][nt], al[mt], bh0, bh1);
                }
            }
        }

#pragma unroll
        for (int mt = 0; mt < 2; mt++)
#pragma unroll
            for (int nt = 0; nt < 4; nt++) {
                int r = wm * 32 + mt * 16 + (lane >> 2);
                int cl = wn * 32 + nt * 8 + (lane & 3) * 2;
                Cs[r * 65 + cl]           = ac2[mt][nt][0];
                Cs[r * 65 + cl + 1]       = ac2[mt][nt][1];
                Cs[(r + 8) * 65 + cl]     = ac2[mt][nt][2];
                Cs[(r + 8) * 65 + cl + 1] = ac2[mt][nt][3];
            }
        __syncthreads();

        // write ctx split bf16, layout (b, l, a), coalesced over a
#pragma unroll
        for (int i = 0; i < 32; i++) {
            int e = i * 256 + tid;
            int a = e & 63, l = e >> 6;
            float v = Cs[l * 65 + a];
            bf16 hi, lo; split2(v, hi, lo);
            size_t off = ((size_t)b * L_ + l0 + l) * 512 + a0 + a;
            g_cxh[off] = hi; g_cxl[off] = lo;
        }
        __syncthreads();
    }
}

// ---------------------------------------------------------------------------
extern "C" void kernel_launch(void* const* d_in, const int* in_sizes, int n_in,
                              void* d_out, int out_size) {
    (void)in_sizes; (void)n_in; (void)out_size;
    const float* x      = (const float*)d_in[0];
    const float* we     = (const float*)d_in[1];
    const float* img    = (const float*)d_in[2];
    /* d_in[3] prev_attn unused */
    const float* conv_v = (const float*)d_in[4];
    const float* conv_g = (const float*)d_in[5];
    const float* conv_b = (const float*)d_in[6];
    const float* fc1_w  = (const float*)d_in[7];
    const float* fc1_b  = (const float*)d_in[8];
    const float* fc2_w  = (const float*)d_in[9];
    const float* fc2_b  = (const float*)d_in[10];
    float* out = (float*)d_out;

    // passthrough copies
    cudaMemcpyAsync(out + OUT_WE, we, (size_t)B_ * L_ * DW * sizeof(float),
                    cudaMemcpyDeviceToDevice, 0);
    cudaMemcpyAsync(out + OUT_IMG, img, (size_t)B_ * DW * HW * sizeof(float),
                    cudaMemcpyDeviceToDevice, 0);

    void *p_w1p, *p_w2p;
    cudaGetSymbolAddress(&p_w1p, g_w1p);
    cudaGetSymbolAddress(&p_w2p, g_w2p);

    // prep
    wnorm_kernel<<<COUT, 256>>>(conv_v, conv_g);
    pack_conv_kernel<<<dim3(80, 8), 256>>>();
    pack_fc_kernel<<<dim3(16, 4), 256>>>(fc1_w, (bf16*)p_w1p);
    pack_fc_kernel<<<dim3(16, 4), 256>>>(fc2_w, (bf16*)p_w2p);
    xT_kernel<<<dim3(L_ / 32, CIN / 32, B_), dim3(32, 8)>>>(x);
    featT_kernel<<<dim3(PP / 32, 512 / 32, B_), dim3(32, 8)>>>(img);
    featpad_kernel<<<(B_ * 512 * PP + 255) / 256, 256>>>(img);

    // opt-in dynamic smem
    cudaFuncSetAttribute(conv_gemm, cudaFuncAttributeMaxDynamicSharedMemorySize, CONV_SMEM);
    cudaFuncSetAttribute(fc_gemm<1>, cudaFuncAttributeMaxDynamicSharedMemorySize, FC_SMEM);
    cudaFuncSetAttribute(fc_gemm<2>, cudaFuncAttributeMaxDynamicSharedMemorySize, FC_SMEM);
    cudaFuncSetAttribute(attn_tc_kernel, cudaFuncAttributeMaxDynamicSharedMemorySize,
                         ATTN_SMEM_BYTES);

    // conv + GLU  (M=1024 interleaved, N=1024, K=2560)
    conv_gemm<<<dim3(L_ / 128, 8, B_), 256, CONV_SMEM>>>(conv_b);
    // fc1 (M=512, N=1024, K=512) -> q bf16 (b,l,a)
    fc_gemm<1><<<dim3(L_ / 128, 4, B_), 256, FC_SMEM>>>(fc1_b, we, nullptr);
    // tensor-core attention -> attn output + ctx (b,l,a)
    attn_tc_kernel<<<dim3(L_ / 128, B_), 256, ATTN_SMEM_BYTES>>>(out + OUT_ATTN);
    // fc2 + residuals (M=512, N=1024, K=512)
    fc_gemm<2><<<dim3(L_ / 128, 4, B_), 256, FC_SMEM>>>(fc2_b, x, out);
}